// round 9
// baseline (speedup 1.0000x reference)
#include <cuda_runtime.h>

// x: (B=64, NU=32, IC=256, UNIT=128) fp32, contiguous.
// Reference reinterprets flat buffer as (B, IC, NU, UNIT):
//   u_hat[b,i,j,u] = x_flat[b*1048576 + i*4096 + j*128 + u]
// s[b,j,u] = (1/256) * sum_i u_hat[b,i,j,u]; then squash over u (128 elems).
// Output: (B, NU, UNIT) = 262144 fp32.
//
// R9 (final tune of the R5/R8 family): one 128-thread block per (b,j)
// group, 2048 blocks, warps i-interleaved (i = warp + 4k), __ldcs.
// FOUR independent float4 accumulators + k+=4 loop (16 LDG.128 visible
// per unrolled region) — fills the 64-reg budget that
// __launch_bounds__(128, 8) grants: 16 accum regs + 16 in-flight load
// regs. Quarters the FADD recurrence vs R5, doubles front-batching vs R8.
// Evidence so far: 6.3-6.5 TB/s plateau across 5 structures (strided and
// sequential); this targets the last ~2% of intra-warp latency exposure.

static constexpr int IC       = 256;
static constexpr int GROUPS   = 64 * 32;        // 2048 blocks
static constexpr int STRIDE4  = 4096 / 4;       // i-stride in float4 units
static constexpr int THREADS  = 128;            // 4 warps/block
static constexpr int IC_PER_W = IC / 4;         // 64 rows per warp

__global__ __launch_bounds__(THREADS, 8)
void capsule_squash_kernel(const float4* __restrict__ x4,
                           float4* __restrict__ out4) {
    const int g    = blockIdx.x;                // group = b*32 + j
    const int warp = threadIdx.x >> 5;
    const int lane = threadIdx.x & 31;

    const int b = g >> 5;
    const int j = g & 31;
    // warp w reads rows i = w, w+4, w+8, ... (interleaved across warps)
    const int base4 = b * (1048576 / 4) + j * (128 / 4) + lane
                    + warp * STRIDE4;

    float4 s0 = make_float4(0.f, 0.f, 0.f, 0.f);
    float4 s1 = make_float4(0.f, 0.f, 0.f, 0.f);
    float4 s2 = make_float4(0.f, 0.f, 0.f, 0.f);
    float4 s3 = make_float4(0.f, 0.f, 0.f, 0.f);

#pragma unroll 4
    for (int k = 0; k < IC_PER_W; k += 4) {
        float4 v0 = __ldcs(&x4[base4 + (k    ) * (4 * STRIDE4)]);
        float4 v1 = __ldcs(&x4[base4 + (k + 1) * (4 * STRIDE4)]);
        float4 v2 = __ldcs(&x4[base4 + (k + 2) * (4 * STRIDE4)]);
        float4 v3 = __ldcs(&x4[base4 + (k + 3) * (4 * STRIDE4)]);
        s0.x += v0.x; s0.y += v0.y; s0.z += v0.z; s0.w += v0.w;
        s1.x += v1.x; s1.y += v1.y; s1.z += v1.z; s1.w += v1.w;
        s2.x += v2.x; s2.y += v2.y; s2.z += v2.z; s2.w += v2.w;
        s3.x += v3.x; s3.y += v3.y; s3.z += v3.z; s3.w += v3.w;
    }

    float4 s = make_float4((s0.x + s1.x) + (s2.x + s3.x),
                           (s0.y + s1.y) + (s2.y + s3.y),
                           (s0.z + s1.z) + (s2.z + s3.z),
                           (s0.w + s1.w) + (s2.w + s3.w));

    __shared__ float4 part[4][32];
    part[warp][lane] = s;
    __syncthreads();

    if (warp == 0) {
        float4 t = part[0][lane];
#pragma unroll
        for (int w = 1; w < 4; w++) {
            float4 p = part[w][lane];
            t.x += p.x; t.y += p.y; t.z += p.z; t.w += p.w;
        }
        const float c = 1.0f / 256.0f;
        t.x *= c; t.y *= c; t.z *= c; t.w *= c;

        // mag_sq over the 128-element unit dim (warp-wide)
        float sq = t.x * t.x + t.y * t.y + t.z * t.z + t.w * t.w;
#pragma unroll
        for (int off = 16; off > 0; off >>= 1)
            sq += __shfl_xor_sync(0xffffffffu, sq, off);

        const float mag   = sqrtf(sq);
        const float scale = sq / (1.0f + sq) / (mag + 1e-5f);

        out4[g * 32 + lane] = make_float4(t.x * scale, t.y * scale,
                                          t.z * scale, t.w * scale);
    }
}

extern "C" void kernel_launch(void* const* d_in, const int* in_sizes, int n_in,
                              void* d_out, int out_size) {
    const float4* x4 = (const float4*)d_in[0];
    float4* out4 = (float4*)d_out;
    capsule_squash_kernel<<<GROUPS, THREADS>>>(x4, out4);
}

// round 10
// speedup vs baseline: 1.0156x; 1.0156x over previous
#include <cuda_runtime.h>

// x: (B=64, NU=32, IC=256, UNIT=128) fp32, contiguous.
// Reference reinterprets flat buffer as (B, IC, NU, UNIT):
//   u_hat[b,i,j,u] = x_flat[b*1048576 + i*4096 + j*128 + u]
// s[b,j,u] = (1/256) * sum_i u_hat[b,i,j,u]; then squash over u (128 elems).
// Output: (B, NU, UNIT) = 262144 fp32.
//
// R10: merge of the two proven wins. 256-thread blocks (8 warps), one block
// per (b,j) group (2048 blocks). Warps i-INTERLEAVED (i = warp + 8k) so the
// block's live window is 8 CONSECUTIVE rows x 512B (vs 4 in R5/R8) — the
// densest HBM-page window of the series. Dual independent accumulators +
// __launch_bounds__(256,4) (64-reg budget) for front-batched loads (the R8
// win). __ldcs streaming. 4 blocks/SM x 8 warps = 32 resident warps/SM.
// Evidence: 6 structures plateau at 6.3-6.5 TB/s; R8 best (6514 GB/s,
// DRAM 82.3%). This is the last untested combination on the live axis.

static constexpr int IC       = 256;
static constexpr int GROUPS   = 64 * 32;        // 2048 blocks
static constexpr int STRIDE4  = 4096 / 4;       // i-stride in float4 units
static constexpr int THREADS  = 256;            // 8 warps/block
static constexpr int IC_PER_W = IC / 8;         // 32 rows per warp

__global__ __launch_bounds__(THREADS, 4)
void capsule_squash_kernel(const float4* __restrict__ x4,
                           float4* __restrict__ out4) {
    const int g    = blockIdx.x;                // group = b*32 + j
    const int warp = threadIdx.x >> 5;
    const int lane = threadIdx.x & 31;

    const int b = g >> 5;
    const int j = g & 31;
    // warp w reads rows i = w, w+8, w+16, ... (interleaved across 8 warps)
    const int base4 = b * (1048576 / 4) + j * (128 / 4) + lane
                    + warp * STRIDE4;

    float4 sA = make_float4(0.f, 0.f, 0.f, 0.f);
    float4 sB = make_float4(0.f, 0.f, 0.f, 0.f);

#pragma unroll 8
    for (int k = 0; k < IC_PER_W; k += 2) {
        float4 vA = __ldcs(&x4[base4 + (k    ) * (8 * STRIDE4)]);
        float4 vB = __ldcs(&x4[base4 + (k + 1) * (8 * STRIDE4)]);
        sA.x += vA.x; sA.y += vA.y; sA.z += vA.z; sA.w += vA.w;
        sB.x += vB.x; sB.y += vB.y; sB.z += vB.z; sB.w += vB.w;
    }
    float4 s = make_float4(sA.x + sB.x, sA.y + sB.y,
                           sA.z + sB.z, sA.w + sB.w);

    __shared__ float4 part[8][32];
    part[warp][lane] = s;
    __syncthreads();

    if (warp == 0) {
        float4 t = part[0][lane];
#pragma unroll
        for (int w = 1; w < 8; w++) {
            float4 p = part[w][lane];
            t.x += p.x; t.y += p.y; t.z += p.z; t.w += p.w;
        }
        const float c = 1.0f / 256.0f;
        t.x *= c; t.y *= c; t.z *= c; t.w *= c;

        // mag_sq over the 128-element unit dim (warp-wide)
        float sq = t.x * t.x + t.y * t.y + t.z * t.z + t.w * t.w;
#pragma unroll
        for (int off = 16; off > 0; off >>= 1)
            sq += __shfl_xor_sync(0xffffffffu, sq, off);

        const float mag   = sqrtf(sq);
        const float scale = sq / (1.0f + sq) / (mag + 1e-5f);

        out4[g * 32 + lane] = make_float4(t.x * scale, t.y * scale,
                                          t.z * scale, t.w * scale);
    }
}

extern "C" void kernel_launch(void* const* d_in, const int* in_sizes, int n_in,
                              void* d_out, int out_size) {
    const float4* x4 = (const float4*)d_in[0];
    float4* out4 = (float4*)d_out;
    capsule_squash_kernel<<<GROUPS, THREADS>>>(x4, out4);
}